// round 6
// baseline (speedup 1.0000x reference)
#include <cuda_runtime.h>
#include <cstdint>

// Geometry (fixed by dataset): B=32, C=3, H=W=512
#define HW4_SHIFT 16
#define HW4       (1 << HW4_SHIFT)            // 65536 float4-groups per plane
#define NPIX      (32LL * 512 * 512)          // 8,388,608 pixels

#define THREADS   256
#define NBLOCKS   8192                        // 1 float4-group per thread

__device__ float4       g_partials4[NBLOCKS / 4];   // viewed as float[NBLOCKS]
__device__ unsigned int g_ticket;                    // zero-init, reset by last block

// Release-only ticket: orders this thread's prior global stores into L2
// before the increment. NO acquire -> no L1 coherence action per block.
__device__ __forceinline__ unsigned int ticket_release(unsigned int* p) {
    unsigned int old;
    asm volatile("atom.release.gpu.global.add.u32 %0, [%1], 1;"
                 : "=r"(old) : "l"(p) : "memory");
    return old;
}

// Hue in SIX-units: returns 6*h where h = (hue/6 mod 1). Range [0,6).
__device__ __forceinline__ float hue6(float r, float g, float b) {
    float maxc  = fmaxf(r, fmaxf(g, b));
    float minc  = fminf(r, fminf(g, b));
    float delta = maxc - minc;
    float safe  = (delta == 0.0f) ? 1.0f : delta;
    float inv;
    asm("rcp.approx.f32 %0, %1;" : "=f"(inv) : "f"(safe));

    float cr = (g - b) * inv;                 // [-1, 1]; ==0 when delta==0 (safe=1)
    float cg = fmaf(b - r, inv, 2.0f);        // [ 1, 3]
    float cb = fmaf(r - g, inv, 4.0f);        // [ 3, 5]

    // delta==0 -> maxc==r -> picks cr==0: matches reference's h=0 case for free.
    float h = (maxc == r) ? cr : ((maxc == g) ? cg : cb);
    return (h < 0.0f) ? h + 6.0f : h;         // mod 6 (only cr can be negative)
}

// Contribution in six-units; global 1/6 factor deferred to the final divide.
__device__ __forceinline__ float pix_loss6(float hp6, float ht6) {
    float d6 = fabsf(hp6 - ht6);
    return (d6 < 3.0f) ? d6 : (d6 - 3.0f);    // d6==3 contributes 0 either way
}

__global__ __launch_bounds__(THREADS)
void hsv_loss_fused(const float4* __restrict__ pred,
                    const float4* __restrict__ targ,
                    float* __restrict__ out) {
    int gid = blockIdx.x * THREADS + threadIdx.x;   // one float4 group per thread
    int b   = gid >> HW4_SHIFT;
    int p4  = gid & (HW4 - 1);
    long long base = ((long long)b * 3) * HW4 + p4;

    // 6 independent LDG.128, front-batched
    float4 pr = pred[base];
    float4 pg = pred[base + HW4];
    float4 pb = pred[base + 2 * HW4];
    float4 tr = targ[base];
    float4 tg = targ[base + HW4];
    float4 tb = targ[base + 2 * HW4];

    float acc;
    acc  = pix_loss6(hue6(pr.x, pg.x, pb.x), hue6(tr.x, tg.x, tb.x));
    acc += pix_loss6(hue6(pr.y, pg.y, pb.y), hue6(tr.y, tg.y, tb.y));
    acc += pix_loss6(hue6(pr.z, pg.z, pb.z), hue6(tr.z, tg.z, tb.z));
    acc += pix_loss6(hue6(pr.w, pg.w, pb.w), hue6(tr.w, tg.w, tb.w));

    // ---- block reduce ----
    #pragma unroll
    for (int off = 16; off > 0; off >>= 1)
        acc += __shfl_xor_sync(0xFFFFFFFFu, acc, off);

    __shared__ float swarp[THREADS / 32];
    int lane = threadIdx.x & 31;
    int wid  = threadIdx.x >> 5;
    if (lane == 0) swarp[wid] = acc;
    __syncthreads();

    __shared__ bool isLast;
    if (threadIdx.x == 0) {
        float v = 0.0f;
        #pragma unroll
        for (int w = 0; w < THREADS / 32; w++) v += swarp[w];
        ((float*)g_partials4)[blockIdx.x] = v;          // write-through to L2
        unsigned int t = ticket_release(&g_ticket);     // release-only, cheap
        isLast = (t == NBLOCKS - 1);
    }
    __syncthreads();

    // ---- last block: single acquire fence, then L2 (.cv) float4 loads ----
    if (isLast) {
        if (threadIdx.x == 0)
            asm volatile("fence.acq_rel.gpu;" ::: "memory");  // one per GRID
        __syncthreads();

        double dacc = 0.0;
        #pragma unroll
        for (int k = 0; k < NBLOCKS / 4 / THREADS; k++) {     // 8 indep LDG.128.cv
            float4 v = __ldcv(&g_partials4[k * THREADS + threadIdx.x]);
            dacc += (double)((v.x + v.y) + (v.z + v.w));
        }

        #pragma unroll
        for (int off = 16; off > 0; off >>= 1)
            dacc += __shfl_xor_sync(0xFFFFFFFFu, dacc, off);

        __shared__ double sd[THREADS / 32];
        if (lane == 0) sd[wid] = dacc;
        __syncthreads();
        if (threadIdx.x == 0) {
            double v = 0.0;
            #pragma unroll
            for (int w = 0; w < THREADS / 32; w++) v += sd[w];
            out[0] = (float)(v / (6.0 * (double)NPIX));   // deferred 1/6
            g_ticket = 0;                                 // reset for next replay
        }
    }
}

extern "C" void kernel_launch(void* const* d_in, const int* in_sizes, int n_in,
                              void* d_out, int out_size) {
    const float4* pred = (const float4*)d_in[0];
    const float4* targ = (const float4*)d_in[1];
    float* out = (float*)d_out;
    hsv_loss_fused<<<NBLOCKS, THREADS>>>(pred, targ, out);
}

// round 7
// speedup vs baseline: 1.2786x; 1.2786x over previous
#include <cuda_runtime.h>
#include <cstdint>

// Geometry (fixed by dataset): B=32, C=3, H=W=512
#define HW4_SHIFT 16
#define HW4       (1 << HW4_SHIFT)            // 65536 float4-groups per plane
#define NPIX      (32LL * 512 * 512)          // 8,388,608 pixels

#define THREADS   256
#define NBLOCKS   8192                        // 1 float4-group per thread

#define FIN_THREADS 1024                      // finish: 8192 floats / 1024 = 2 float4/thr

__device__ float4 g_partials4[NBLOCKS / 4];   // viewed as float[NBLOCKS]

// Hue in SIX-units: returns 6*h where h = (hue/6 mod 1). Range [0,6).
__device__ __forceinline__ float hue6(float r, float g, float b) {
    float maxc  = fmaxf(r, fmaxf(g, b));
    float minc  = fminf(r, fminf(g, b));
    float delta = maxc - minc;
    float safe  = (delta == 0.0f) ? 1.0f : delta;
    float inv;
    asm("rcp.approx.f32 %0, %1;" : "=f"(inv) : "f"(safe));

    float cr = (g - b) * inv;                 // [-1, 1]; ==0 when delta==0 (safe=1)
    float cg = fmaf(b - r, inv, 2.0f);        // [ 1, 3]
    float cb = fmaf(r - g, inv, 4.0f);        // [ 3, 5]

    // delta==0 -> maxc==r -> picks cr==0: matches reference's h=0 case for free.
    float h = (maxc == r) ? cr : ((maxc == g) ? cg : cb);
    return (h < 0.0f) ? h + 6.0f : h;         // mod 6 (only cr can be negative)
}

// Contribution in six-units; global 1/6 factor deferred to the final divide.
__device__ __forceinline__ float pix_loss6(float hp6, float ht6) {
    float d6 = fabsf(hp6 - ht6);
    return (d6 < 3.0f) ? d6 : (d6 - 3.0f);    // d6==3 contributes 0 either way
}

__global__ __launch_bounds__(THREADS)
void hsv_loss_main(const float4* __restrict__ pred,
                   const float4* __restrict__ targ) {
    int gid = blockIdx.x * THREADS + threadIdx.x;   // one float4 group per thread
    int b   = gid >> HW4_SHIFT;
    int p4  = gid & (HW4 - 1);
    long long base = ((long long)b * 3) * HW4 + p4;

    // 6 independent LDG.128, front-batched
    float4 pr = pred[base];
    float4 pg = pred[base + HW4];
    float4 pb = pred[base + 2 * HW4];
    float4 tr = targ[base];
    float4 tg = targ[base + HW4];
    float4 tb = targ[base + 2 * HW4];

    float acc;
    acc  = pix_loss6(hue6(pr.x, pg.x, pb.x), hue6(tr.x, tg.x, tb.x));
    acc += pix_loss6(hue6(pr.y, pg.y, pb.y), hue6(tr.y, tg.y, tb.y));
    acc += pix_loss6(hue6(pr.z, pg.z, pb.z), hue6(tr.z, tg.z, tb.z));
    acc += pix_loss6(hue6(pr.w, pg.w, pb.w), hue6(tr.w, tg.w, tb.w));

    // ---- block reduce ----
    #pragma unroll
    for (int off = 16; off > 0; off >>= 1)
        acc += __shfl_xor_sync(0xFFFFFFFFu, acc, off);

    __shared__ float swarp[THREADS / 32];
    int lane = threadIdx.x & 31;
    int wid  = threadIdx.x >> 5;
    if (lane == 0) swarp[wid] = acc;
    __syncthreads();
    if (wid == 0) {
        float v = (lane < THREADS / 32) ? swarp[lane] : 0.0f;
        #pragma unroll
        for (int off = 4; off > 0; off >>= 1)
            v += __shfl_xor_sync(0xFFFFFFFFu, v, off);
        if (lane == 0) ((float*)g_partials4)[blockIdx.x] = v;
    }
}

__global__ __launch_bounds__(FIN_THREADS)
void hsv_loss_finish(float* __restrict__ out) {
    // 2048 float4 partial-groups, 1024 threads -> 2 independent LDG.128 each.
    float4 v0 = g_partials4[threadIdx.x];
    float4 v1 = g_partials4[threadIdx.x + FIN_THREADS];
    double dacc = (double)((v0.x + v0.y) + (v0.z + v0.w))
                + (double)((v1.x + v1.y) + (v1.z + v1.w));

    #pragma unroll
    for (int off = 16; off > 0; off >>= 1)
        dacc += __shfl_xor_sync(0xFFFFFFFFu, dacc, off);

    __shared__ double sd[FIN_THREADS / 32];
    int lane = threadIdx.x & 31;
    int wid  = threadIdx.x >> 5;
    if (lane == 0) sd[wid] = dacc;
    __syncthreads();
    if (wid == 0) {
        double v = (lane < FIN_THREADS / 32) ? sd[lane] : 0.0;
        #pragma unroll
        for (int off = 16; off > 0; off >>= 1)
            v += __shfl_xor_sync(0xFFFFFFFFu, v, off);
        if (lane == 0)
            out[0] = (float)(v / (6.0 * (double)NPIX));   // deferred 1/6
    }
}

extern "C" void kernel_launch(void* const* d_in, const int* in_sizes, int n_in,
                              void* d_out, int out_size) {
    const float4* pred = (const float4*)d_in[0];
    const float4* targ = (const float4*)d_in[1];
    float* out = (float*)d_out;
    hsv_loss_main<<<NBLOCKS, THREADS>>>(pred, targ);
    hsv_loss_finish<<<1, FIN_THREADS>>>(out);
}

// round 8
// speedup vs baseline: 1.2808x; 1.0017x over previous
#include <cuda_runtime.h>
#include <cstdint>

// Geometry (fixed by dataset): B=32, C=3, H=W=512
#define HW4_SHIFT 16
#define HW4       (1 << HW4_SHIFT)            // 65536 float4-groups per plane
#define NPIX      (32LL * 512 * 512)          // 8,388,608 pixels

#define THREADS   256
#define NBLOCKS   8192                        // 1 float4-group per thread

#define FIN_THREADS 1024                      // finish: 8192 floats -> 2 float4/thr

__device__ float4 g_partials4[NBLOCKS / 4];   // viewed as float[NBLOCKS]

// Hue in SIX-units: returns 6*h where h = (hue/6 mod 1). Range [0,6).
__device__ __forceinline__ float hue6(float r, float g, float b) {
    float maxc  = fmaxf(r, fmaxf(g, b));
    float minc  = fminf(r, fminf(g, b));
    float delta = maxc - minc;
    float safe  = (delta == 0.0f) ? 1.0f : delta;
    float inv;
    asm("rcp.approx.f32 %0, %1;" : "=f"(inv) : "f"(safe));

    float cr = (g - b) * inv;                 // [-1, 1]; ==0 when delta==0 (safe=1)
    float cg = fmaf(b - r, inv, 2.0f);        // [ 1, 3]
    float cb = fmaf(r - g, inv, 4.0f);        // [ 3, 5]

    // delta==0 -> maxc==r -> picks cr==0: matches reference's h=0 case for free.
    float h = (maxc == r) ? cr : ((maxc == g) ? cg : cb);
    return (h < 0.0f) ? h + 6.0f : h;         // mod 6 (only cr can be negative)
}

// Contribution in six-units; global 1/6 factor deferred to the final divide.
__device__ __forceinline__ float pix_loss6(float hp6, float ht6) {
    float d6 = fabsf(hp6 - ht6);
    return (d6 < 3.0f) ? d6 : (d6 - 3.0f);    // d6==3 contributes 0 either way
}

__global__ __launch_bounds__(THREADS)
void hsv_loss_main(const float4* __restrict__ pred,
                   const float4* __restrict__ targ) {
    // PDL: let the dependent (finish) kernel launch NOW and pre-stage; its
    // griddepcontrol.wait still blocks until this grid fully completes.
    asm volatile("griddepcontrol.launch_dependents;");

    int gid = blockIdx.x * THREADS + threadIdx.x;   // one float4 group per thread
    int b   = gid >> HW4_SHIFT;
    int p4  = gid & (HW4 - 1);
    long long base = ((long long)b * 3) * HW4 + p4;

    // 6 independent LDG.128, front-batched
    float4 pr = pred[base];
    float4 pg = pred[base + HW4];
    float4 pb = pred[base + 2 * HW4];
    float4 tr = targ[base];
    float4 tg = targ[base + HW4];
    float4 tb = targ[base + 2 * HW4];

    float acc;
    acc  = pix_loss6(hue6(pr.x, pg.x, pb.x), hue6(tr.x, tg.x, tb.x));
    acc += pix_loss6(hue6(pr.y, pg.y, pb.y), hue6(tr.y, tg.y, tb.y));
    acc += pix_loss6(hue6(pr.z, pg.z, pb.z), hue6(tr.z, tg.z, tb.z));
    acc += pix_loss6(hue6(pr.w, pg.w, pb.w), hue6(tr.w, tg.w, tb.w));

    // ---- block reduce ----
    #pragma unroll
    for (int off = 16; off > 0; off >>= 1)
        acc += __shfl_xor_sync(0xFFFFFFFFu, acc, off);

    __shared__ float swarp[THREADS / 32];
    int lane = threadIdx.x & 31;
    int wid  = threadIdx.x >> 5;
    if (lane == 0) swarp[wid] = acc;
    __syncthreads();
    if (wid == 0) {
        float v = (lane < THREADS / 32) ? swarp[lane] : 0.0f;
        #pragma unroll
        for (int off = 4; off > 0; off >>= 1)
            v += __shfl_xor_sync(0xFFFFFFFFu, v, off);
        if (lane == 0)
            __stcg(&((float*)g_partials4)[blockIdx.x], v);   // L1-bypass store
    }
}

__global__ __launch_bounds__(FIN_THREADS)
void hsv_loss_finish(float* __restrict__ out) {
    // Pre-staged under PDL; block here until the main grid's memory is visible.
    asm volatile("griddepcontrol.wait;");

    // 2048 float4 partial-groups, 1024 threads -> 2 independent LDG.128 each.
    float4 v0 = g_partials4[threadIdx.x];
    float4 v1 = g_partials4[threadIdx.x + FIN_THREADS];
    double dacc = (double)((v0.x + v0.y) + (v0.z + v0.w))
                + (double)((v1.x + v1.y) + (v1.z + v1.w));

    #pragma unroll
    for (int off = 16; off > 0; off >>= 1)
        dacc += __shfl_xor_sync(0xFFFFFFFFu, dacc, off);

    __shared__ double sd[FIN_THREADS / 32];
    int lane = threadIdx.x & 31;
    int wid  = threadIdx.x >> 5;
    if (lane == 0) sd[wid] = dacc;
    __syncthreads();
    if (wid == 0) {
        double v = (lane < FIN_THREADS / 32) ? sd[lane] : 0.0;
        #pragma unroll
        for (int off = 16; off > 0; off >>= 1)
            v += __shfl_xor_sync(0xFFFFFFFFu, v, off);
        if (lane == 0)
            out[0] = (float)(v / (6.0 * (double)NPIX));   // deferred 1/6
    }
}

extern "C" void kernel_launch(void* const* d_in, const int* in_sizes, int n_in,
                              void* d_out, int out_size) {
    const float4* pred = (const float4*)d_in[0];
    const float4* targ = (const float4*)d_in[1];
    float* out = (float*)d_out;

    hsv_loss_main<<<NBLOCKS, THREADS>>>(pred, targ);

    // Finish kernel with Programmatic Dependent Launch (overlaps its launch
    // latency with the main kernel; graph-capture supported).
    cudaLaunchConfig_t cfg = {};
    cfg.gridDim  = dim3(1, 1, 1);
    cfg.blockDim = dim3(FIN_THREADS, 1, 1);
    cfg.dynamicSmemBytes = 0;
    cfg.stream = 0;
    cudaLaunchAttribute attr[1];
    attr[0].id = cudaLaunchAttributeProgrammaticStreamSerialization;
    attr[0].val.programmaticStreamSerializationAllowed = 1;
    cfg.attrs = attr;
    cfg.numAttrs = 1;
    cudaLaunchKernelEx(&cfg, hsv_loss_finish, out);
}

// round 9
// speedup vs baseline: 1.3551x; 1.0580x over previous
#include <cuda_runtime.h>
#include <cstdint>

// Geometry (fixed by dataset): B=32, C=3, H=W=512
#define HW4_SHIFT 16
#define HW4       (1 << HW4_SHIFT)            // 65536 float4-groups per plane
#define NPIX_F    8388608.0f                  // 32*512*512 pixels

#define THREADS   256
#define NBLOCKS   8192                        // 1 float4-group per thread

__device__ float        g_accum;              // zero-init; reset by winner
__device__ unsigned int g_ticket;             // zero-init; reset by winner

// Hue in SIX-units: returns 6*h where h = (hue/6 mod 1). Range [0,6).
__device__ __forceinline__ float hue6(float r, float g, float b) {
    float maxc  = fmaxf(r, fmaxf(g, b));
    float minc  = fminf(r, fminf(g, b));
    float delta = maxc - minc;
    float safe  = (delta == 0.0f) ? 1.0f : delta;
    float inv;
    asm("rcp.approx.f32 %0, %1;" : "=f"(inv) : "f"(safe));

    float cr = (g - b) * inv;                 // [-1, 1]; ==0 when delta==0 (safe=1)
    float cg = fmaf(b - r, inv, 2.0f);        // [ 1, 3]
    float cb = fmaf(r - g, inv, 4.0f);        // [ 3, 5]

    // delta==0 -> maxc==r -> picks cr==0: matches reference's h=0 case for free.
    float h = (maxc == r) ? cr : ((maxc == g) ? cg : cb);
    return (h < 0.0f) ? h + 6.0f : h;         // mod 6 (only cr can be negative)
}

// Contribution in six-units; global 1/6 factor deferred to the final scale.
__device__ __forceinline__ float pix_loss6(float hp6, float ht6) {
    float d6 = fabsf(hp6 - ht6);
    return (d6 < 3.0f) ? d6 : (d6 - 3.0f);    // d6==3 contributes 0 either way
}

__global__ __launch_bounds__(THREADS)
void hsv_loss_onepass(const float4* __restrict__ pred,
                      const float4* __restrict__ targ,
                      float* __restrict__ out) {
    int gid = blockIdx.x * THREADS + threadIdx.x;   // one float4 group per thread
    int b   = gid >> HW4_SHIFT;
    int p4  = gid & (HW4 - 1);
    long long base = ((long long)b * 3) * HW4 + p4;

    // 6 independent LDG.128, front-batched
    float4 pr = pred[base];
    float4 pg = pred[base + HW4];
    float4 pb = pred[base + 2 * HW4];
    float4 tr = targ[base];
    float4 tg = targ[base + HW4];
    float4 tb = targ[base + 2 * HW4];

    float acc;
    acc  = pix_loss6(hue6(pr.x, pg.x, pb.x), hue6(tr.x, tg.x, tb.x));
    acc += pix_loss6(hue6(pr.y, pg.y, pb.y), hue6(tr.y, tg.y, tb.y));
    acc += pix_loss6(hue6(pr.z, pg.z, pb.z), hue6(tr.z, tg.z, tb.z));
    acc += pix_loss6(hue6(pr.w, pg.w, pb.w), hue6(tr.w, tg.w, tb.w));

    // ---- block reduce ----
    #pragma unroll
    for (int off = 16; off > 0; off >>= 1)
        acc += __shfl_xor_sync(0xFFFFFFFFu, acc, off);

    __shared__ float swarp[THREADS / 32];
    int lane = threadIdx.x & 31;
    int wid  = threadIdx.x >> 5;
    if (lane == 0) swarp[wid] = acc;
    __syncthreads();

    if (threadIdx.x == 0) {
        float v = (swarp[0] + swarp[1]) + (swarp[2] + swarp[3])
                + ((swarp[4] + swarp[5]) + (swarp[6] + swarp[7]));

        // Fire-and-forget float add into the global accumulator (REDG, no return).
        asm volatile("red.global.gpu.add.f32 [%0], %1;"
                     :: "l"(&g_accum), "f"(v) : "memory");

        // Release ticket: orders this block's red.add before the increment.
        unsigned int t;
        asm volatile("atom.release.gpu.global.add.u32 %0, [%1], 1;"
                     : "=r"(t) : "l"(&g_ticket) : "memory");

        if (t == NBLOCKS - 1) {               // exactly one thread in the grid
            asm volatile("fence.acq_rel.gpu;" ::: "memory");
            float s;
            asm volatile("ld.global.cv.f32 %0, [%1];" : "=f"(s) : "l"(&g_accum));
            out[0] = s * (1.0f / (6.0f * NPIX_F));
            // reset for the next graph replay (kernel boundary publishes these)
            asm volatile("st.global.cg.f32 [%0], 0f00000000;" :: "l"(&g_accum) : "memory");
            asm volatile("st.global.cg.u32 [%0], 0;" :: "l"(&g_ticket) : "memory");
        }
    }
}

extern "C" void kernel_launch(void* const* d_in, const int* in_sizes, int n_in,
                              void* d_out, int out_size) {
    const float4* pred = (const float4*)d_in[0];
    const float4* targ = (const float4*)d_in[1];
    float* out = (float*)d_out;
    hsv_loss_onepass<<<NBLOCKS, THREADS>>>(pred, targ, out);
}